// round 1
// baseline (speedup 1.0000x reference)
#include <cuda_runtime.h>
#include <cuda_bf16.h>

// Fully fused: conv1(3->16,3x3,pad1)+GELU  ->  conv2(16->18,3x3,pad1)  ->
// deformable bilinear sampling of pm25, all in one kernel per 16x16 tile.
// conv2 work is computed per-tap and skipped when the deform weight for that
// tap is exactly zero (warp-uniform branch; correct for any weight).

#define TS 16           // output tile side
#define HT (TS + 2)     // h tile side (conv2 halo)
#define IT (TS + 4)     // input tile side (conv1 halo of h tile)
#define HH 512
#define WW 512
#define HWS (HH * WW)

__global__ __launch_bounds__(256, 4)
void fused_residual_advection(const float* __restrict__ pm25,
                              const float* __restrict__ wind,
                              const float* __restrict__ topo,
                              const float* __restrict__ w1,
                              const float* __restrict__ b1,
                              const float* __restrict__ w2,
                              const float* __restrict__ b2,
                              const float* __restrict__ wt,
                              float* __restrict__ out) {
    __shared__ float s_in[3][IT][IT];       // zero-padded offset_input tile
    __shared__ float s_h[16][HT][HT];       // gelu(conv1) tile, channel-plane major
    __shared__ float s_w1[432];             // (16,3,3,3)
    __shared__ float s_w2[2592];            // (18,16,3,3)
    __shared__ float s_b1[16];
    __shared__ float s_b2[18];
    __shared__ float s_wt[9];

    const int tid = threadIdx.x;
    const int b   = blockIdx.z;
    const int ty0 = blockIdx.y * TS;
    const int tx0 = blockIdx.x * TS;

    // ---- load weights into smem ----
    for (int i = tid; i < 432;  i += 256) s_w1[i] = w1[i];
    for (int i = tid; i < 2592; i += 256) s_w2[i] = w2[i];
    if (tid < 16)                       s_b1[tid]      = b1[tid];
    else if (tid >= 32 && tid < 50)     s_b2[tid - 32] = b2[tid - 32];
    else if (tid >= 64 && tid < 73)     s_wt[tid - 64] = wt[tid - 64];

    // ---- load zero-padded input tile: channels [wind0, wind1, topo] ----
    const float* windb = wind + (size_t)b * 2 * HWS;
    const float* topob = topo + (size_t)b * HWS;
    for (int i = tid; i < 3 * IT * IT; i += 256) {
        int c  = i / (IT * IT);
        int r  = i - c * (IT * IT);
        int iy = r / IT, ix = r - iy * IT;
        int gy = ty0 - 2 + iy, gx = tx0 - 2 + ix;
        float v = 0.f;
        if ((unsigned)gy < HH && (unsigned)gx < WW) {
            v = (c < 2) ? windb[c * HWS + gy * WW + gx] : topob[gy * WW + gx];
        }
        s_in[c][iy][ix] = v;
    }
    __syncthreads();

    // ---- stage 1: h = gelu(conv1(input)) on the (TS+2)^2 halo tile ----
    // h outside the image must be ZERO (conv2 zero-pads h, not conv1-of-zeros).
    for (int p = tid; p < HT * HT; p += 256) {
        int hy = p / HT, hx = p - hy * HT;
        int gy = ty0 - 1 + hy, gx = tx0 - 1 + hx;
        if ((unsigned)gy >= HH || (unsigned)gx >= WW) {
            #pragma unroll
            for (int o = 0; o < 16; o++) s_h[o][hy][hx] = 0.f;
        } else {
            float in_reg[27];
            #pragma unroll
            for (int c = 0; c < 3; c++)
                #pragma unroll
                for (int ky = 0; ky < 3; ky++)
                    #pragma unroll
                    for (int kx = 0; kx < 3; kx++)
                        in_reg[(c * 3 + ky) * 3 + kx] = s_in[c][hy + ky][hx + kx];
            #pragma unroll
            for (int o = 0; o < 16; o++) {
                float acc = s_b1[o];
                #pragma unroll
                for (int t = 0; t < 27; t++)
                    acc = fmaf(in_reg[t], s_w1[o * 27 + t], acc);
                // exact GELU: x * Phi(x)
                s_h[o][hy][hx] = acc * normcdff(acc);
            }
        }
    }
    __syncthreads();

    // ---- stage 2: per output pixel, per nonzero tap: conv2 (2 ch) + bilinear ----
    const int lx = tid & (TS - 1);
    const int ly = tid >> 4;
    const int gy = ty0 + ly;
    const int gx = tx0 + lx;
    const float* pimg = pm25 + (size_t)b * HWS;

    float acc_out = 0.f;
    #pragma unroll 1
    for (int k = 0; k < 9; k++) {
        float wk = s_wt[k];
        if (wk == 0.f) continue;   // warp-uniform skip

        float dyv = s_b2[2 * k];
        float dxv = s_b2[2 * k + 1];
        const float* w2k = s_w2 + 2 * k * 144;   // channel 2k, then 2k+1 at +144
        #pragma unroll
        for (int ky = 0; ky < 3; ky++) {
            #pragma unroll
            for (int kx = 0; kx < 3; kx++) {
                const int wi = ky * 3 + kx;
                #pragma unroll
                for (int ci = 0; ci < 16; ci++) {
                    float hv = s_h[ci][ly + ky][lx + kx];
                    dyv = fmaf(hv, w2k[ci * 9 + wi], dyv);
                    dxv = fmaf(hv, w2k[144 + ci * 9 + wi], dxv);
                }
            }
        }

        float py = (float)(gy + (k / 3) - 1) + dyv;
        float px = (float)(gx + (k % 3) - 1) + dxv;
        float y0f = floorf(py), x0f = floorf(px);
        float wy1 = py - y0f,   wx1 = px - x0f;
        int y0 = (int)y0f, x0 = (int)x0f;
        int y1 = y0 + 1,   x1 = x0 + 1;

        bool vy0 = (unsigned)y0 < HH, vy1 = (unsigned)y1 < HH;
        bool vx0 = (unsigned)x0 < WW, vx1 = (unsigned)x1 < WW;
        int yc0 = min(max(y0, 0), HH - 1), yc1 = min(max(y1, 0), HH - 1);
        int xc0 = min(max(x0, 0), WW - 1), xc1 = min(max(x1, 0), WW - 1);
        const float* r0 = pimg + yc0 * WW;
        const float* r1 = pimg + yc1 * WW;
        float v00 = (vy0 && vx0) ? r0[xc0] : 0.f;
        float v01 = (vy0 && vx1) ? r0[xc1] : 0.f;
        float v10 = (vy1 && vx0) ? r1[xc0] : 0.f;
        float v11 = (vy1 && vx1) ? r1[xc1] : 0.f;

        float samp = (1.f - wy1) * (1.f - wx1) * v00
                   + (1.f - wy1) * wx1         * v01
                   + wy1         * (1.f - wx1) * v10
                   + wy1         * wx1         * v11;
        acc_out = fmaf(samp, wk, acc_out);
    }

    out[(size_t)b * HWS + gy * WW + gx] = acc_out;
}

extern "C" void kernel_launch(void* const* d_in, const int* in_sizes, int n_in,
                              void* d_out, int out_size) {
    const float* pm25 = (const float*)d_in[0];
    const float* wind = (const float*)d_in[1];
    const float* topo = (const float*)d_in[2];
    const float* w1   = (const float*)d_in[3];
    const float* b1   = (const float*)d_in[4];
    const float* w2   = (const float*)d_in[5];
    const float* b2   = (const float*)d_in[6];
    const float* wt   = (const float*)d_in[7];
    float* out        = (float*)d_out;

    int B = in_sizes[0] / (HH * WW);
    dim3 grid(WW / TS, HH / TS, B);
    fused_residual_advection<<<grid, 256>>>(pm25, wind, topo, w1, b1, w2, b2, wt, out);
}

// round 4
// speedup vs baseline: 1.9373x; 1.9373x over previous
#include <cuda_runtime.h>
#include <cuda_bf16.h>

// Fused: conv1(3->16,3x3)+exact GELU -> conv2(16->18,3x3) -> deformable
// bilinear sampling. Weights live in __constant__ (uniform LDCU path, off the
// smem crossbar). 32x16 output tile, 256 threads, 2 output px per thread.

#define TSX 32
#define TSY 16
#define HTX (TSX + 2)   // 34  h tile width
#define HTY (TSY + 2)   // 18  h tile height
#define HPITCH 34       // h row pitch (floats) — even, so float2 loads stay aligned
#define ITX (TSX + 4)   // 36  input tile width
#define ITY (TSY + 4)   // 20  input tile height
#define HH 512
#define WW 512
#define HWS (HH * WW)

__constant__ float c_w1[432];    // (16,3,3,3)
__constant__ float c_b1[16];
__constant__ float c_w2[2592];   // (18,16,3,3)
__constant__ float c_b2[18];
__constant__ float c_wt[9];

__global__ __launch_bounds__(256, 4)
void fused_residual_advection(const float* __restrict__ pm25,
                              const float* __restrict__ wind,
                              const float* __restrict__ topo,
                              float* __restrict__ out) {
    __shared__ float s_in[3][ITY][ITX];          // 8640 B zero-padded offset_input tile
    __shared__ float s_h[16][HTY][HPITCH];       // 39168 B gelu(conv1), channel-plane major

    const int tid = threadIdx.x;
    const int b   = blockIdx.z;
    const int ty0 = blockIdx.y * TSY;
    const int tx0 = blockIdx.x * TSX;

    // ---- load zero-padded input tile: channels [wind0, wind1, topo] ----
    const float* windb = wind + (size_t)b * 2 * HWS;
    const float* topob = topo + (size_t)b * HWS;
    for (int i = tid; i < 3 * ITY * ITX; i += 256) {
        int c  = i / (ITY * ITX);
        int r  = i - c * (ITY * ITX);
        int iy = r / ITX, ix = r - iy * ITX;
        int gy = ty0 - 2 + iy, gx = tx0 - 2 + ix;
        float v = 0.f;
        if ((unsigned)gy < HH && (unsigned)gx < WW) {
            v = (c < 2) ? windb[c * HWS + gy * WW + gx] : topob[gy * WW + gx];
        }
        s_in[c][iy][ix] = v;
    }
    __syncthreads();

    // ---- stage 1: h = gelu(conv1(input)) on the 18x34 halo tile ----
    // h outside the image must be ZERO (conv2 zero-pads h itself).
    for (int p = tid; p < HTY * HTX; p += 256) {
        int hy = p / HTX, hx = p - hy * HTX;
        int gy = ty0 - 1 + hy, gx = tx0 - 1 + hx;
        if ((unsigned)gy >= HH || (unsigned)gx >= WW) {
            #pragma unroll
            for (int o = 0; o < 16; o++) s_h[o][hy][hx] = 0.f;
        } else {
            float in_reg[27];
            #pragma unroll
            for (int c = 0; c < 3; c++)
                #pragma unroll
                for (int ky = 0; ky < 3; ky++)
                    #pragma unroll
                    for (int kx = 0; kx < 3; kx++)
                        in_reg[(c * 3 + ky) * 3 + kx] = s_in[c][hy + ky][hx + kx];
            #pragma unroll
            for (int o = 0; o < 16; o++) {
                float acc = c_b1[o];
                #pragma unroll
                for (int t = 0; t < 27; t++)
                    acc = fmaf(in_reg[t], c_w1[o * 27 + t], acc);
                s_h[o][hy][hx] = acc * normcdff(acc);   // exact GELU
            }
        }
    }
    __syncthreads();

    // ---- stage 2: each thread computes 2 horizontally-adjacent outputs ----
    const int py  = tid >> 4;            // 0..15
    const int px2 = (tid & 15) * 2;      // 0,2,...,30
    const int gy  = ty0 + py;
    const int gx0 = tx0 + px2;
    const float* pimg = pm25 + (size_t)b * HWS;

    float out0 = 0.f, out1 = 0.f;
    #pragma unroll 1
    for (int k = 0; k < 9; k++) {
        float wk = c_wt[k];
        if (wk == 0.f) continue;         // warp-uniform skip

        // conv2 channels (2k, 2k+1) at the two pixels
        float dy0 = c_b2[2 * k],     dy1 = dy0;
        float dx0 = c_b2[2 * k + 1], dx1 = dx0;
        const int wbase_y = (2 * k) * 144;
        const int wbase_x = (2 * k + 1) * 144;
        #pragma unroll
        for (int ky = 0; ky < 3; ky++) {
            #pragma unroll
            for (int ci = 0; ci < 16; ci++) {
                const float2 a = *(const float2*)&s_h[ci][py + ky][px2];
                const float2 c = *(const float2*)&s_h[ci][py + ky][px2 + 2];
                const int wi = ci * 9 + ky * 3;
                float wy0 = c_w2[wbase_y + wi + 0];
                float wy1 = c_w2[wbase_y + wi + 1];
                float wy2 = c_w2[wbase_y + wi + 2];
                float wx0 = c_w2[wbase_x + wi + 0];
                float wx1 = c_w2[wbase_x + wi + 1];
                float wx2 = c_w2[wbase_x + wi + 2];
                dy0 = fmaf(a.x, wy0, dy0); dy0 = fmaf(a.y, wy1, dy0); dy0 = fmaf(c.x, wy2, dy0);
                dy1 = fmaf(a.y, wy0, dy1); dy1 = fmaf(c.x, wy1, dy1); dy1 = fmaf(c.y, wy2, dy1);
                dx0 = fmaf(a.x, wx0, dx0); dx0 = fmaf(a.y, wx1, dx0); dx0 = fmaf(c.x, wx2, dx0);
                dx1 = fmaf(a.y, wx0, dx1); dx1 = fmaf(c.x, wx1, dx1); dx1 = fmaf(c.y, wx2, dx1);
            }
        }

        const float kyo = (float)(k / 3 - 1);
        const float kxo = (float)(k % 3 - 1);
        #pragma unroll
        for (int px = 0; px < 2; px++) {
            float dyv = px ? dy1 : dy0;
            float dxv = px ? dx1 : dx0;
            float py_ = (float)gy + kyo + dyv;
            float px_ = (float)(gx0 + px) + kxo + dxv;
            float y0f = floorf(py_), x0f = floorf(px_);
            float wy = py_ - y0f, wx = px_ - x0f;
            int y0 = (int)y0f, x0 = (int)x0f;
            int y1 = y0 + 1,   x1 = x0 + 1;
            bool vy0 = (unsigned)y0 < HH, vy1 = (unsigned)y1 < HH;
            bool vx0 = (unsigned)x0 < WW, vx1 = (unsigned)x1 < WW;
            int yc0 = min(max(y0, 0), HH - 1), yc1 = min(max(y1, 0), HH - 1);
            int xc0 = min(max(x0, 0), WW - 1), xc1 = min(max(x1, 0), WW - 1);
            const float* r0 = pimg + yc0 * WW;
            const float* r1 = pimg + yc1 * WW;
            float v00 = (vy0 && vx0) ? r0[xc0] : 0.f;
            float v01 = (vy0 && vx1) ? r0[xc1] : 0.f;
            float v10 = (vy1 && vx0) ? r1[xc0] : 0.f;
            float v11 = (vy1 && vx1) ? r1[xc1] : 0.f;
            float samp = (1.f - wy) * (1.f - wx) * v00
                       + (1.f - wy) * wx         * v01
                       + wy         * (1.f - wx) * v10
                       + wy         * wx         * v11;
            if (px) out1 = fmaf(samp, wk, out1);
            else    out0 = fmaf(samp, wk, out0);
        }
    }

    *(float2*)&out[(size_t)b * HWS + (size_t)gy * WW + gx0] = make_float2(out0, out1);
}

extern "C" void kernel_launch(void* const* d_in, const int* in_sizes, int n_in,
                              void* d_out, int out_size) {
    const float* pm25 = (const float*)d_in[0];
    const float* wind = (const float*)d_in[1];
    const float* topo = (const float*)d_in[2];

    cudaMemcpyToSymbolAsync(c_w1, d_in[3], 432  * sizeof(float), 0, cudaMemcpyDeviceToDevice);
    cudaMemcpyToSymbolAsync(c_b1, d_in[4], 16   * sizeof(float), 0, cudaMemcpyDeviceToDevice);
    cudaMemcpyToSymbolAsync(c_w2, d_in[5], 2592 * sizeof(float), 0, cudaMemcpyDeviceToDevice);
    cudaMemcpyToSymbolAsync(c_b2, d_in[6], 18   * sizeof(float), 0, cudaMemcpyDeviceToDevice);
    cudaMemcpyToSymbolAsync(c_wt, d_in[7], 9    * sizeof(float), 0, cudaMemcpyDeviceToDevice);

    float* out = (float*)d_out;
    int B = in_sizes[0] / (HH * WW);
    dim3 grid(WW / TSX, HH / TSY, B);
    fused_residual_advection<<<grid, 256>>>(pm25, wind, topo, out);
}